// round 1
// baseline (speedup 1.0000x reference)
#include <cuda_runtime.h>
#include <math.h>

// ---------------------------------------------------------------------------
// Problem constants (fixed by setup_inputs)
// ---------------------------------------------------------------------------
#define Bb    2
#define Cd    768
#define Lh    4096            // H*W
#define Mrows (Bb*Lh)         // 8192
#define TWOD  1536
#define DBLW  56              // DT_RANK + 2*N_STATE
#define RK    48
#define NS    4
#define NCh   64              // scan chunks per batch
#define LCh   64              // chunk length  (NCh*LCh == Lh)

// ---------------------------------------------------------------------------
// Static device scratch (no cudaMalloc allowed)
// ---------------------------------------------------------------------------
__device__ float g_xt  [2][Mrows*Cd];     // x transposed to (B,L,C)
__device__ float g_xn  [2][Mrows*Cd];     // layernormed x
__device__ float g_mean[2][Mrows];
__device__ float g_rstd[2][Mrows];
__device__ float g_uz  [2][Mrows*TWOD];   // in_proj output
__device__ float g_u   [2][Mrows*Cd];     // conv+silu output
__device__ float g_dbl [2][Mrows*DBLW];   // dt_raw | B | C
__device__ float g_dt  [2][Mrows*Cd];     // softplus dt
__device__ float g_yz  [2][Mrows*Cd];     // y * silu(z)
__device__ float g_P   [2][Bb*Cd*NCh*NS]; // per-chunk decay product
__device__ float g_Hc  [2][Bb*Cd*NCh*NS]; // per-chunk h_end -> h_init

// ---------------------------------------------------------------------------
// LayerNorm stats: one thread per (b,l) row, coalesced over l per channel
// ---------------------------------------------------------------------------
__global__ void ln_stats_k(const float* __restrict__ x,
                           float* __restrict__ mean, float* __restrict__ rstd)
{
    int r = blockIdx.x * blockDim.x + threadIdx.x;
    if (r >= Mrows) return;
    int b = r / Lh, l = r % Lh;
    const float* xp = x + (size_t)b * Cd * Lh + l;
    float s = 0.f, s2 = 0.f;
#pragma unroll 8
    for (int c = 0; c < Cd; c++) {
        float v = __ldg(xp + (size_t)c * Lh);
        s += v;
        s2 = fmaf(v, v, s2);
    }
    float m   = s * (1.f / Cd);
    float var = s2 * (1.f / Cd) - m * m;
    mean[r] = m;
    rstd[r] = rsqrtf(var + 1e-5f);
}

// ---------------------------------------------------------------------------
// Transpose BCHW(=B,C,L) -> (B,L,C); writes raw xt (residual) and normed xn
// ---------------------------------------------------------------------------
__global__ void tn_k(const float* __restrict__ x,
                     const float* __restrict__ mean, const float* __restrict__ rstd,
                     const float* __restrict__ g, const float* __restrict__ lb,
                     float* __restrict__ xt, float* __restrict__ xn)
{
    __shared__ float t[32][33];
    int b  = blockIdx.z;
    int c0 = blockIdx.y * 32;
    int l0 = blockIdx.x * 32;
#pragma unroll
    for (int i = 0; i < 4; i++) {
        int c = c0 + threadIdx.y + i * 8;
        t[threadIdx.y + i * 8][threadIdx.x] =
            x[((size_t)b * Cd + c) * Lh + l0 + threadIdx.x];
    }
    __syncthreads();
#pragma unroll
    for (int i = 0; i < 4; i++) {
        int l = l0 + threadIdx.y + i * 8;
        int c = c0 + threadIdx.x;
        int r = b * Lh + l;
        float v = t[threadIdx.x][threadIdx.y + i * 8];
        size_t o = (size_t)r * Cd + c;
        xt[o] = v;
        xn[o] = (v - mean[r]) * rstd[r] * g[c] + lb[c];
    }
}

// ---------------------------------------------------------------------------
// Generic tiled fp32 GEMM: C[M,N] = A[M,K] @ W[K,N], optional epilogue
//   EPI 0: plain store
//   EPI 1: softplus(acc + aux[n])
//   EPI 2: acc + aux[r*ldc + n]   (residual add)
// BM=BN=64, BK=16, 256 threads, 4x4 per thread.
// Requires: M % 64 == 0, K % 16 == 0, lda/N row strides multiple of 4 floats.
// ---------------------------------------------------------------------------
template<int EPI>
__global__ void __launch_bounds__(256)
gemm_k(const float* __restrict__ A, int lda,
       const float* __restrict__ W,
       float* __restrict__ Cout, int ldc,
       int Mn, int Nn, int Kn,
       const float* __restrict__ aux)
{
    __shared__ float As[16][68];
    __shared__ float Bs[16][68];
    int tid = threadIdx.x;
    int tx = tid & 15, ty = tid >> 4;
    int row0 = blockIdx.y * 64;
    int col0 = blockIdx.x * 64;

    float acc[4][4] = {};

    for (int kt = 0; kt < Kn; kt += 16) {
        // A tile: 64 rows x 16 k (one float4 per thread)
        {
            int m  = tid >> 2;
            int k4 = (tid & 3) * 4;
            float4 v = *(const float4*)(A + (size_t)(row0 + m) * lda + kt + k4);
            As[k4 + 0][m] = v.x;
            As[k4 + 1][m] = v.y;
            As[k4 + 2][m] = v.z;
            As[k4 + 3][m] = v.w;
        }
        // B tile: 16 k x 64 n (one float4 per thread)
        {
            int kk = tid >> 4;
            int n4 = (tid & 15) * 4;
            int gn = col0 + n4;
            const float* wp = W + (size_t)(kt + kk) * Nn;
            float4 v = make_float4(0.f, 0.f, 0.f, 0.f);
            if (gn + 3 < Nn) {
                v = *(const float4*)(wp + gn);
            } else {
                if (gn + 0 < Nn) v.x = wp[gn + 0];
                if (gn + 1 < Nn) v.y = wp[gn + 1];
                if (gn + 2 < Nn) v.z = wp[gn + 2];
                if (gn + 3 < Nn) v.w = wp[gn + 3];
            }
            *(float4*)&Bs[kk][n4] = v;
        }
        __syncthreads();
#pragma unroll
        for (int k = 0; k < 16; k++) {
            float4 a = *(const float4*)&As[k][ty * 4];
            float4 bv = *(const float4*)&Bs[k][tx * 4];
            float av[4] = {a.x, a.y, a.z, a.w};
            float bw[4] = {bv.x, bv.y, bv.z, bv.w};
#pragma unroll
            for (int i = 0; i < 4; i++)
#pragma unroll
                for (int j = 0; j < 4; j++)
                    acc[i][j] = fmaf(av[i], bw[j], acc[i][j]);
        }
        __syncthreads();
    }

#pragma unroll
    for (int i = 0; i < 4; i++) {
        int r = row0 + ty * 4 + i;
        if (r >= Mn) continue;
#pragma unroll
        for (int j = 0; j < 4; j++) {
            int c = col0 + tx * 4 + j;
            if (c >= Nn) continue;
            float v = acc[i][j];
            if (EPI == 1) {
                v += aux[c];
                v = fmaxf(v, 0.f) + log1pf(__expf(-fabsf(v)));
            } else if (EPI == 2) {
                v += aux[(size_t)r * ldc + c];
            }
            Cout[(size_t)r * ldc + c] = v;
        }
    }
}

// ---------------------------------------------------------------------------
// Depthwise causal conv (K=4) along L within each batch + bias + SiLU.
// Reads u = uz[:, 0:768], writes g_u.
// ---------------------------------------------------------------------------
__global__ void conv_silu_k(const float* __restrict__ uz,
                            const float* __restrict__ wc,
                            const float* __restrict__ bc,
                            float* __restrict__ uo)
{
    int idx = blockIdx.x * blockDim.x + threadIdx.x;
    if (idx >= Mrows * Cd) return;
    int d = idx % Cd;
    int r = idx / Cd;
    int l = r % Lh;
    float w0 = wc[d * 4 + 0], w1 = wc[d * 4 + 1];
    float w2 = wc[d * 4 + 2], w3 = wc[d * 4 + 3];
    const float* base = uz + (size_t)r * TWOD + d;
    float v = bc[d];
    if (l >= 3) v = fmaf(base[-3 * TWOD], w0, v);
    if (l >= 2) v = fmaf(base[-2 * TWOD], w1, v);
    if (l >= 1) v = fmaf(base[-1 * TWOD], w2, v);
    v = fmaf(base[0], w3, v);
    float s = 1.f / (1.f + __expf(-v));
    uo[idx] = v * s;
}

// ---------------------------------------------------------------------------
// Selective scan phase 1: per (b, d, chunk) compute decay product P and
// chunk-local end state Hend (h_init = 0).
// ---------------------------------------------------------------------------
__global__ void scan1_k(const float* __restrict__ dt, const float* __restrict__ u,
                        const float* __restrict__ dbl,
                        const float* __restrict__ Alog,
                        float* __restrict__ Pout, float* __restrict__ Hout)
{
    int d  = blockIdx.z * 256 + threadIdx.x;   // 0..767
    int ch = blockIdx.x;                       // 0..63
    int b  = blockIdx.y;                       // 0..1
    float An[NS];
#pragma unroll
    for (int n = 0; n < NS; n++) An[n] = -__expf(Alog[d * NS + n]);
    float h[NS] = {0.f, 0.f, 0.f, 0.f};
    float P[NS] = {1.f, 1.f, 1.f, 1.f};
    int l0 = ch * LCh;
    for (int l = l0; l < l0 + LCh; l++) {
        int r = b * Lh + l;
        float dtv = dt[(size_t)r * Cd + d];
        float uv  = u [(size_t)r * Cd + d];
        float du  = dtv * uv;
        const float* Bp = dbl + (size_t)r * DBLW + RK;
#pragma unroll
        for (int n = 0; n < NS; n++) {
            float dA = __expf(dtv * An[n]);
            h[n] = fmaf(dA, h[n], du * Bp[n]);
            P[n] *= dA;
        }
    }
    size_t o = (((size_t)(b * Cd + d)) * NCh + ch) * NS;
#pragma unroll
    for (int n = 0; n < NS; n++) { Pout[o + n] = P[n]; Hout[o + n] = h[n]; }
}

// ---------------------------------------------------------------------------
// Phase 2: cross-chunk scan per (b,d). Overwrites Hc with h_init per chunk.
// ---------------------------------------------------------------------------
__global__ void scan2_k(const float* __restrict__ P, float* __restrict__ Hc)
{
    int idx = blockIdx.x * 256 + threadIdx.x;  // b*Cd + d, 0..1535
    if (idx >= Bb * Cd) return;
    float h[NS] = {0.f, 0.f, 0.f, 0.f};
    size_t base = (size_t)idx * NCh * NS;
    for (int ch = 0; ch < NCh; ch++) {
        size_t o = base + ch * NS;
#pragma unroll
        for (int n = 0; n < NS; n++) {
            float He = Hc[o + n];
            float Pv = P[o + n];
            Hc[o + n] = h[n];               // h_init for this chunk
            h[n] = fmaf(Pv, h[n], He);
        }
    }
}

// ---------------------------------------------------------------------------
// Phase 3: replay chunks with correct h_init, read out with OTHER stream's C,
// add D-skip, gate with silu(z), write yz.
// ---------------------------------------------------------------------------
__global__ void scan3_k(const float* __restrict__ dt, const float* __restrict__ u,
                        const float* __restrict__ dbl_self,
                        const float* __restrict__ dbl_other,
                        const float* __restrict__ Hc,
                        const float* __restrict__ Alog,
                        const float* __restrict__ Dskip,
                        const float* __restrict__ uz,
                        float* __restrict__ yz)
{
    int d  = blockIdx.z * 256 + threadIdx.x;
    int ch = blockIdx.x;
    int b  = blockIdx.y;
    float An[NS];
#pragma unroll
    for (int n = 0; n < NS; n++) An[n] = -__expf(Alog[d * NS + n]);
    float h[NS];
    size_t ho = (((size_t)(b * Cd + d)) * NCh + ch) * NS;
#pragma unroll
    for (int n = 0; n < NS; n++) h[n] = Hc[ho + n];
    float dsk = Dskip[d];
    int l0 = ch * LCh;
    for (int l = l0; l < l0 + LCh; l++) {
        int r = b * Lh + l;
        float dtv = dt[(size_t)r * Cd + d];
        float uv  = u [(size_t)r * Cd + d];
        float du  = dtv * uv;
        const float* Bp = dbl_self  + (size_t)r * DBLW + RK;
        const float* Cp = dbl_other + (size_t)r * DBLW + RK + NS;
        float y = uv * dsk;
#pragma unroll
        for (int n = 0; n < NS; n++) {
            float dA = __expf(dtv * An[n]);
            h[n] = fmaf(dA, h[n], du * Bp[n]);
            y = fmaf(h[n], Cp[n], y);
        }
        float z  = uz[(size_t)r * TWOD + Cd + d];
        float sz = z / (1.f + __expf(-z));
        yz[(size_t)r * Cd + d] = y * sz;
    }
}

// ---------------------------------------------------------------------------
// Launch
// ---------------------------------------------------------------------------
extern "C" void kernel_launch(void* const* d_in, const int* in_sizes, int n_in,
                              void* d_out, int out_size)
{
    (void)in_sizes; (void)n_in; (void)out_size;

    float *xt, *xn, *mean, *rstd, *uz, *u, *dbl, *dt, *yz, *P, *Hc;
    cudaGetSymbolAddress((void**)&xt,   g_xt);
    cudaGetSymbolAddress((void**)&xn,   g_xn);
    cudaGetSymbolAddress((void**)&mean, g_mean);
    cudaGetSymbolAddress((void**)&rstd, g_rstd);
    cudaGetSymbolAddress((void**)&uz,   g_uz);
    cudaGetSymbolAddress((void**)&u,    g_u);
    cudaGetSymbolAddress((void**)&dbl,  g_dbl);
    cudaGetSymbolAddress((void**)&dt,   g_dt);
    cudaGetSymbolAddress((void**)&yz,   g_yz);
    cudaGetSymbolAddress((void**)&P,    g_P);
    cudaGetSymbolAddress((void**)&Hc,   g_Hc);

    const size_t SC  = (size_t)Mrows * Cd;    // per-stream stride, C-wide bufs
    const size_t SUZ = (size_t)Mrows * TWOD;
    const size_t SDB = (size_t)Mrows * DBLW;
    const size_t SSC = (size_t)Bb * Cd * NCh * NS;

    const float* Xin[2]  = { (const float*)d_in[0], (const float*)d_in[1] };
    const float* lng[2], *lnb[2], *Win[2], *Wcv[2], *bcv[2], *Wxp[2],
               * Wdt[2], *bdt[2], *Alog[2], *Dsk[2], *Wout[2];
    for (int s = 0; s < 2; s++) {
        int o = 2 + s * 11;
        lng[s]  = (const float*)d_in[o + 0];
        lnb[s]  = (const float*)d_in[o + 1];
        Win[s]  = (const float*)d_in[o + 2];
        Wcv[s]  = (const float*)d_in[o + 3];
        bcv[s]  = (const float*)d_in[o + 4];
        Wxp[s]  = (const float*)d_in[o + 5];
        Wdt[s]  = (const float*)d_in[o + 6];
        bdt[s]  = (const float*)d_in[o + 7];
        Alog[s] = (const float*)d_in[o + 8];
        Dsk[s]  = (const float*)d_in[o + 9];
        Wout[s] = (const float*)d_in[o + 10];
    }

    // ---- per-stream pre-processing ----
    for (int s = 0; s < 2; s++) {
        ln_stats_k<<<(Mrows + 127) / 128, 128>>>(Xin[s], mean + s * Mrows,
                                                 rstd + s * Mrows);
        tn_k<<<dim3(Lh / 32, Cd / 32, Bb), dim3(32, 8)>>>(
            Xin[s], mean + s * Mrows, rstd + s * Mrows, lng[s], lnb[s],
            xt + s * SC, xn + s * SC);

        // in_proj: (8192 x 768) @ (768 x 1536)
        gemm_k<0><<<dim3(TWOD / 64, Mrows / 64), 256>>>(
            xn + s * SC, Cd, Win[s], uz + s * SUZ, TWOD,
            Mrows, TWOD, Cd, nullptr);

        conv_silu_k<<<(Mrows * Cd + 255) / 256, 256>>>(
            uz + s * SUZ, Wcv[s], bcv[s], u + s * SC);

        // x_proj: (8192 x 768) @ (768 x 56)
        gemm_k<0><<<dim3(1, Mrows / 64), 256>>>(
            u + s * SC, Cd, Wxp[s], dbl + s * SDB, DBLW,
            Mrows, DBLW, Cd, nullptr);

        // dt: softplus((8192 x 48) @ (48 x 768) + bdt)
        gemm_k<1><<<dim3(Cd / 64, Mrows / 64), 256>>>(
            dbl + s * SDB, DBLW, Wdt[s], dt + s * SC, Cd,
            Mrows, Cd, RK, bdt[s]);
    }

    // ---- selective scans (cross-modal C) ----
    for (int s = 0; s < 2; s++) {
        scan1_k<<<dim3(NCh, Bb, Cd / 256), 256>>>(
            dt + s * SC, u + s * SC, dbl + s * SDB, Alog[s],
            P + s * SSC, Hc + s * SSC);
        scan2_k<<<(Bb * Cd + 255) / 256, 256>>>(P + s * SSC, Hc + s * SSC);
        scan3_k<<<dim3(NCh, Bb, Cd / 256), 256>>>(
            dt + s * SC, u + s * SC, dbl + s * SDB, dbl + (1 - s) * SDB,
            Hc + s * SSC, Alog[s], Dsk[s], uz + s * SUZ, yz + s * SC);
    }

    // ---- out_proj + residual ----
    for (int s = 0; s < 2; s++) {
        float* outp = (float*)d_out + (size_t)s * Mrows * Cd;
        gemm_k<2><<<dim3(Cd / 64, Mrows / 64), 256>>>(
            yz + s * SC, Cd, Wout[s], outp, Cd,
            Mrows, Cd, Cd, xt + s * SC);
    }
}

// round 3
// speedup vs baseline: 2.5021x; 2.5021x over previous
#include <cuda_runtime.h>
#include <cuda_bf16.h>
#include <math.h>
#include <cstdint>

// ---------------------------------------------------------------------------
// Problem constants (fixed by setup_inputs)
// ---------------------------------------------------------------------------
#define Bb    2
#define Cd    768
#define Lh    4096            // H*W
#define Mrows (Bb*Lh)         // 8192
#define TWOD  1536
#define DBLS  64              // padded dt_raw|B|C row stride (56 -> 64)
#define RK    48
#define NS    4
#define NCh   64              // scan chunks per batch
#define LCh   64              // chunk length  (NCh*LCh == Lh)

// ---------------------------------------------------------------------------
// Static device scratch (no cudaMalloc allowed)
// ---------------------------------------------------------------------------
__device__ float          g_xt  [2][Mrows*Cd];     // residual (B,L,C) fp32
__device__ __nv_bfloat16  g_xnb [2][Mrows*Cd];     // layernormed x, bf16
__device__ float          g_mean[2][Mrows];
__device__ float          g_rstd[2][Mrows];
__device__ float          g_uz  [2][Mrows*TWOD];   // in_proj output fp32
__device__ float          g_u   [2][Mrows*Cd];     // conv+silu fp32 (scan)
__device__ __nv_bfloat16  g_ub  [2][Mrows*Cd];     // conv+silu bf16 (xproj A)
__device__ float          g_dbl [2][Mrows*DBLS];   // dt_raw | B | C (stride 64)
__device__ __nv_bfloat16  g_dtrb[2][Mrows*64];     // dt_raw bf16, K padded to 64
__device__ float          g_dt  [2][Mrows*Cd];     // softplus dt
__device__ __nv_bfloat16  g_yzb [2][Mrows*Cd];     // y * silu(z) bf16
__device__ float          g_P   [2][Bb*Cd*NCh*NS];
__device__ float          g_Hc  [2][Bb*Cd*NCh*NS];
// transposed bf16 weights: Wt[n][k], zero padded
__device__ __nv_bfloat16  g_wint [2][TWOD*Cd];     // in_proj  [1536][768]
__device__ __nv_bfloat16  g_woutt[2][Cd*Cd];       // out_proj [768][768]
__device__ __nv_bfloat16  g_wxpt [2][64*Cd];       // x_proj   [64][768] (56 used)
__device__ __nv_bfloat16  g_wdtt [2][Cd*64];       // dt_proj  [768][64] (48 used)

// ---------------------------------------------------------------------------
// PTX helpers (sm_80-era: cp.async + ldmatrix + mma.sync -- works on sm_103)
// ---------------------------------------------------------------------------
__device__ __forceinline__ uint32_t smem_u32(const void* p) {
    uint32_t a;
    asm("{ .reg .u64 t; cvta.to.shared.u64 t, %1; cvt.u32.u64 %0, t; }"
        : "=r"(a) : "l"(p));
    return a;
}
__device__ __forceinline__ void cpa16(uint32_t s, const void* g) {
    asm volatile("cp.async.cg.shared.global [%0], [%1], 16;" :: "r"(s), "l"(g));
}
__device__ __forceinline__ void cpa_commit() {
    asm volatile("cp.async.commit_group;" ::: "memory");
}
__device__ __forceinline__ void cpa_wait0() {
    asm volatile("cp.async.wait_group 0;" ::: "memory");
}
__device__ __forceinline__ void ldsm4(uint32_t& r0, uint32_t& r1,
                                      uint32_t& r2, uint32_t& r3, uint32_t a) {
    asm volatile("ldmatrix.sync.aligned.m8n8.x4.shared.b16 {%0,%1,%2,%3}, [%4];"
                 : "=r"(r0), "=r"(r1), "=r"(r2), "=r"(r3) : "r"(a));
}
__device__ __forceinline__ void mma16816(float* d, const uint32_t* a,
                                         uint32_t b0, uint32_t b1) {
    asm volatile(
        "mma.sync.aligned.m16n8k16.row.col.f32.bf16.bf16.f32 "
        "{%0,%1,%2,%3}, {%4,%5,%6,%7}, {%8,%9}, {%0,%1,%2,%3};"
        : "+f"(d[0]), "+f"(d[1]), "+f"(d[2]), "+f"(d[3])
        : "r"(a[0]), "r"(a[1]), "r"(a[2]), "r"(a[3]), "r"(b0), "r"(b1));
}

// ---------------------------------------------------------------------------
// LayerNorm stats: one thread per (b,l) row
// ---------------------------------------------------------------------------
__global__ void ln_stats_k(const float* __restrict__ x,
                           float* __restrict__ mean, float* __restrict__ rstd)
{
    int r = blockIdx.x * blockDim.x + threadIdx.x;
    if (r >= Mrows) return;
    int b = r / Lh, l = r % Lh;
    const float* xp = x + (size_t)b * Cd * Lh + l;
    float s = 0.f, s2 = 0.f;
#pragma unroll 8
    for (int c = 0; c < Cd; c++) {
        float v = __ldg(xp + (size_t)c * Lh);
        s += v;
        s2 = fmaf(v, v, s2);
    }
    float m   = s * (1.f / Cd);
    float var = s2 * (1.f / Cd) - m * m;
    mean[r] = m;
    rstd[r] = rsqrtf(var + 1e-5f);
}

// ---------------------------------------------------------------------------
// Transpose BCHW(=B,C,L) -> (B,L,C); fp32 residual xt + bf16 normed xn
// ---------------------------------------------------------------------------
__global__ void tn_k(const float* __restrict__ x,
                     const float* __restrict__ mean, const float* __restrict__ rstd,
                     const float* __restrict__ g, const float* __restrict__ lb,
                     float* __restrict__ xt, __nv_bfloat16* __restrict__ xn)
{
    __shared__ float t[32][33];
    int b  = blockIdx.z;
    int c0 = blockIdx.y * 32;
    int l0 = blockIdx.x * 32;
#pragma unroll
    for (int i = 0; i < 4; i++) {
        int c = c0 + threadIdx.y + i * 8;
        t[threadIdx.y + i * 8][threadIdx.x] =
            x[((size_t)b * Cd + c) * Lh + l0 + threadIdx.x];
    }
    __syncthreads();
#pragma unroll
    for (int i = 0; i < 4; i++) {
        int l = l0 + threadIdx.y + i * 8;
        int c = c0 + threadIdx.x;
        int r = b * Lh + l;
        float v = t[threadIdx.x][threadIdx.y + i * 8];
        size_t o = (size_t)r * Cd + c;
        xt[o] = v;
        xn[o] = __float2bfloat16((v - mean[r]) * rstd[r] * g[c] + lb[c]);
    }
}

// ---------------------------------------------------------------------------
// Weight transpose + fp32->bf16 + zero pad: W[K,N] -> Wt[Npad,Kpad]
// ---------------------------------------------------------------------------
__global__ void wt_k(const float* __restrict__ W, __nv_bfloat16* __restrict__ Wt,
                     int K, int N, int Kpad, int Npad)
{
    __shared__ float t[32][33];
    int k0 = blockIdx.x * 32, n0 = blockIdx.y * 32;
#pragma unroll
    for (int i = 0; i < 4; i++) {
        int k = k0 + threadIdx.y + i * 8;
        int n = n0 + threadIdx.x;
        t[threadIdx.y + i * 8][threadIdx.x] =
            (k < K && n < N) ? W[(size_t)k * N + n] : 0.f;
    }
    __syncthreads();
#pragma unroll
    for (int i = 0; i < 4; i++) {
        int n = n0 + threadIdx.y + i * 8;
        int k = k0 + threadIdx.x;
        if (n < Npad && k < Kpad)
            Wt[(size_t)n * Kpad + k] = __float2bfloat16(t[threadIdx.x][threadIdx.y + i * 8]);
    }
}

// ---------------------------------------------------------------------------
// HMMA bf16 GEMM: C[M,N] = A[M,K] @ Wt[N,K]^T, fp32 accumulate.
//   CTA tile 128 x NT (NT=128 or 64), BK=32, 256 threads = 8 warps (4x2),
//   warp tile 32 x NT/2, cp.async double-buffered smem, ldmatrix fragments.
//   EPI 0: store fp32
//   EPI 1: store fp32 + bf16 copy (stride 64, zero cols >= 48)
//   EPI 2: softplus(v + aux[c])
//   EPI 3: v + aux[r*ldc + c]  (residual)
// Requirements: M%128==0, K%32==0, N==NT*gridDim.x, lda/Kn/ldc 8-elem aligned.
// ---------------------------------------------------------------------------
template<int NT, int EPI>
__global__ void __launch_bounds__(256)
hgemm_k(const __nv_bfloat16* __restrict__ A, int lda,
        const __nv_bfloat16* __restrict__ Wt,
        float* __restrict__ out, int ldc, int Kn,
        const float* __restrict__ aux,
        __nv_bfloat16* __restrict__ out_bf)
{
    constexpr int LDS  = 40;                 // padded smem row (bf16 elems)
    constexpr int AELE = 128 * LDS;
    constexpr int BELE = NT * LDS;
    constexpr int WN   = NT / 2;             // warp n extent
    constexpr int NTL  = WN / 8;             // n8 tiles per warp

    __shared__ __nv_bfloat16 sm[2 * (AELE + BELE)];

    const int tid  = threadIdx.x;
    const int lane = tid & 31;
    const int wid  = tid >> 5;
    const int wm   = wid & 3;                // 0..3  -> 32-row slice
    const int wn   = wid >> 2;               // 0..1  -> WN-col slice

    const int row0 = blockIdx.y * 128;
    const int col0 = blockIdx.x * NT;

    const uint32_t sb = smem_u32(sm);

    // ---- async tile loader ----
    auto issue = [&](int c, int s) {
        const int kt = c * 32;
        const uint32_t sA = sb + (uint32_t)s * (AELE + BELE) * 2;
        const uint32_t sB = sA + AELE * 2;
        const __nv_bfloat16* Ap = A + (size_t)row0 * lda + kt;
#pragma unroll
        for (int i = 0; i < 2; i++) {
            int idx = i * 256 + tid;
            int r = idx >> 2, c8 = (idx & 3) * 8;
            cpa16(sA + (r * LDS + c8) * 2, Ap + (size_t)r * lda + c8);
        }
        const __nv_bfloat16* Bp = Wt + (size_t)col0 * Kn + kt;
#pragma unroll
        for (int i = 0; i < NT / 64; i++) {
            int idx = i * 256 + tid;
            int r = idx >> 2, c8 = (idx & 3) * 8;
            cpa16(sB + (r * LDS + c8) * 2, Bp + (size_t)r * Kn + c8);
        }
        cpa_commit();
    };

    float acc[2][NTL][4];
#pragma unroll
    for (int mi = 0; mi < 2; mi++)
#pragma unroll
        for (int ni = 0; ni < NTL; ni++)
#pragma unroll
            for (int j = 0; j < 4; j++) acc[mi][ni][j] = 0.f;

    const int nch = Kn >> 5;
    issue(0, 0);

    for (int c = 0; c < nch; c++) {
        const int s = c & 1;
        cpa_wait0();
        __syncthreads();
        if (c + 1 < nch) issue(c + 1, 1 - s);

        const uint32_t sA = sb + (uint32_t)s * (AELE + BELE) * 2;
        const uint32_t sB = sA + AELE * 2;

#pragma unroll
        for (int ks = 0; ks < 32; ks += 16) {
            uint32_t a[2][4];
#pragma unroll
            for (int mi = 0; mi < 2; mi++) {
                uint32_t addr = sA +
                    ((wm * 32 + mi * 16 + (lane & 15)) * LDS + ks + (lane >> 4) * 8) * 2;
                ldsm4(a[mi][0], a[mi][1], a[mi][2], a[mi][3], addr);
            }
#pragma unroll
            for (int nj = 0; nj < NTL / 2; nj++) {
                int rB = wn * WN + nj * 16 + (lane & 7) + ((lane >> 4) & 1) * 8;
                uint32_t addr = sB + (rB * LDS + ks + ((lane >> 3) & 1) * 8) * 2;
                uint32_t b0, b1, b2, b3;
                ldsm4(b0, b1, b2, b3, addr);
#pragma unroll
                for (int mi = 0; mi < 2; mi++) {
                    mma16816(acc[mi][nj * 2 + 0], a[mi], b0, b1);
                    mma16816(acc[mi][nj * 2 + 1], a[mi], b2, b3);
                }
            }
        }
        __syncthreads();
    }

    // ---- epilogue ----
#pragma unroll
    for (int mi = 0; mi < 2; mi++) {
        int r = row0 + wm * 32 + mi * 16 + (lane >> 2);
#pragma unroll
        for (int ni = 0; ni < NTL; ni++) {
            int cg = col0 + wn * WN + ni * 8 + (lane & 3) * 2;
#pragma unroll
            for (int half = 0; half < 2; half++) {
                int rr = r + half * 8;
                float v0 = acc[mi][ni][half * 2 + 0];
                float v1 = acc[mi][ni][half * 2 + 1];
                if (EPI == 2) {
                    v0 += aux[cg];     v0 = fmaxf(v0, 0.f) + log1pf(__expf(-fabsf(v0)));
                    v1 += aux[cg + 1]; v1 = fmaxf(v1, 0.f) + log1pf(__expf(-fabsf(v1)));
                } else if (EPI == 3) {
                    const float2 xv = *(const float2*)(aux + (size_t)rr * ldc + cg);
                    v0 += xv.x; v1 += xv.y;
                }
                *(float2*)(out + (size_t)rr * ldc + cg) = make_float2(v0, v1);
                if (EPI == 1) {
                    __nv_bfloat162 pk;
                    pk.x = __float2bfloat16(cg     < RK ? v0 : 0.f);
                    pk.y = __float2bfloat16(cg + 1 < RK ? v1 : 0.f);
                    *(__nv_bfloat162*)(out_bf + (size_t)rr * 64 + cg) = pk;
                }
            }
        }
    }
}

// ---------------------------------------------------------------------------
// Depthwise causal conv (K=4) + bias + SiLU; fp32 and bf16 outputs
// ---------------------------------------------------------------------------
__global__ void conv_silu_k(const float* __restrict__ uz,
                            const float* __restrict__ wc,
                            const float* __restrict__ bc,
                            float* __restrict__ uo,
                            __nv_bfloat16* __restrict__ ub)
{
    int idx = blockIdx.x * blockDim.x + threadIdx.x;
    if (idx >= Mrows * Cd) return;
    int d = idx % Cd;
    int r = idx / Cd;
    int l = r % Lh;
    float w0 = wc[d * 4 + 0], w1 = wc[d * 4 + 1];
    float w2 = wc[d * 4 + 2], w3 = wc[d * 4 + 3];
    const float* base = uz + (size_t)r * TWOD + d;
    float v = bc[d];
    if (l >= 3) v = fmaf(base[-3 * TWOD], w0, v);
    if (l >= 2) v = fmaf(base[-2 * TWOD], w1, v);
    if (l >= 1) v = fmaf(base[-1 * TWOD], w2, v);
    v = fmaf(base[0], w3, v);
    float sv = v / (1.f + __expf(-v));
    uo[idx] = sv;
    ub[idx] = __float2bfloat16(sv);
}

// ---------------------------------------------------------------------------
// Selective scan phase 1
// ---------------------------------------------------------------------------
__global__ void scan1_k(const float* __restrict__ dt, const float* __restrict__ u,
                        const float* __restrict__ dbl,
                        const float* __restrict__ Alog,
                        float* __restrict__ Pout, float* __restrict__ Hout)
{
    int d  = blockIdx.z * 256 + threadIdx.x;
    int ch = blockIdx.x;
    int b  = blockIdx.y;
    float An[NS];
#pragma unroll
    for (int n = 0; n < NS; n++) An[n] = -__expf(Alog[d * NS + n]);
    float h[NS] = {0.f, 0.f, 0.f, 0.f};
    float P[NS] = {1.f, 1.f, 1.f, 1.f};
    int l0 = ch * LCh;
    for (int l = l0; l < l0 + LCh; l++) {
        int r = b * Lh + l;
        float dtv = dt[(size_t)r * Cd + d];
        float uv  = u [(size_t)r * Cd + d];
        float du  = dtv * uv;
        const float* Bp = dbl + (size_t)r * DBLS + RK;
#pragma unroll
        for (int n = 0; n < NS; n++) {
            float dA = __expf(dtv * An[n]);
            h[n] = fmaf(dA, h[n], du * Bp[n]);
            P[n] *= dA;
        }
    }
    size_t o = (((size_t)(b * Cd + d)) * NCh + ch) * NS;
#pragma unroll
    for (int n = 0; n < NS; n++) { Pout[o + n] = P[n]; Hout[o + n] = h[n]; }
}

// ---------------------------------------------------------------------------
// Phase 2: cross-chunk scan per (b,d)
// ---------------------------------------------------------------------------
__global__ void scan2_k(const float* __restrict__ P, float* __restrict__ Hc)
{
    int idx = blockIdx.x * 256 + threadIdx.x;
    if (idx >= Bb * Cd) return;
    float h[NS] = {0.f, 0.f, 0.f, 0.f};
    size_t base = (size_t)idx * NCh * NS;
    for (int ch = 0; ch < NCh; ch++) {
        size_t o = base + ch * NS;
#pragma unroll
        for (int n = 0; n < NS; n++) {
            float He = Hc[o + n];
            float Pv = P[o + n];
            Hc[o + n] = h[n];
            h[n] = fmaf(Pv, h[n], He);
        }
    }
}

// ---------------------------------------------------------------------------
// Phase 3: replay + cross-C readout + D-skip + silu(z) gate -> bf16 yz
// ---------------------------------------------------------------------------
__global__ void scan3_k(const float* __restrict__ dt, const float* __restrict__ u,
                        const float* __restrict__ dbl_self,
                        const float* __restrict__ dbl_other,
                        const float* __restrict__ Hc,
                        const float* __restrict__ Alog,
                        const float* __restrict__ Dskip,
                        const float* __restrict__ uz,
                        __nv_bfloat16* __restrict__ yz)
{
    int d  = blockIdx.z * 256 + threadIdx.x;
    int ch = blockIdx.x;
    int b  = blockIdx.y;
    float An[NS];
#pragma unroll
    for (int n = 0; n < NS; n++) An[n] = -__expf(Alog[d * NS + n]);
    float h[NS];
    size_t ho = (((size_t)(b * Cd + d)) * NCh + ch) * NS;
#pragma unroll
    for (int n = 0; n < NS; n++) h[n] = Hc[ho + n];
    float dsk = Dskip[d];
    int l0 = ch * LCh;
    for (int l = l0; l < l0 + LCh; l++) {
        int r = b * Lh + l;
        float dtv = dt[(size_t)r * Cd + d];
        float uv  = u [(size_t)r * Cd + d];
        float du  = dtv * uv;
        const float* Bp = dbl_self  + (size_t)r * DBLS + RK;
        const float* Cp = dbl_other + (size_t)r * DBLS + RK + NS;
        float y = uv * dsk;
#pragma unroll
        for (int n = 0; n < NS; n++) {
            float dA = __expf(dtv * An[n]);
            h[n] = fmaf(dA, h[n], du * Bp[n]);
            y = fmaf(h[n], Cp[n], y);
        }
        float z  = uz[(size_t)r * TWOD + Cd + d];
        float sz = z / (1.f + __expf(-z));
        yz[(size_t)r * Cd + d] = __float2bfloat16(y * sz);
    }
}

// ---------------------------------------------------------------------------
// Launch
// ---------------------------------------------------------------------------
extern "C" void kernel_launch(void* const* d_in, const int* in_sizes, int n_in,
                              void* d_out, int out_size)
{
    (void)in_sizes; (void)n_in; (void)out_size;

    float *xt, *mean, *rstd, *uz, *u, *dbl, *dt, *P, *Hc;
    __nv_bfloat16 *xnb, *ub, *dtrb, *yzb, *wint, *woutt, *wxpt, *wdtt;
    cudaGetSymbolAddress((void**)&xt,    g_xt);
    cudaGetSymbolAddress((void**)&xnb,   g_xnb);
    cudaGetSymbolAddress((void**)&mean,  g_mean);
    cudaGetSymbolAddress((void**)&rstd,  g_rstd);
    cudaGetSymbolAddress((void**)&uz,    g_uz);
    cudaGetSymbolAddress((void**)&u,     g_u);
    cudaGetSymbolAddress((void**)&ub,    g_ub);
    cudaGetSymbolAddress((void**)&dbl,   g_dbl);
    cudaGetSymbolAddress((void**)&dtrb,  g_dtrb);
    cudaGetSymbolAddress((void**)&dt,    g_dt);
    cudaGetSymbolAddress((void**)&yzb,   g_yzb);
    cudaGetSymbolAddress((void**)&P,     g_P);
    cudaGetSymbolAddress((void**)&Hc,    g_Hc);
    cudaGetSymbolAddress((void**)&wint,  g_wint);
    cudaGetSymbolAddress((void**)&woutt, g_woutt);
    cudaGetSymbolAddress((void**)&wxpt,  g_wxpt);
    cudaGetSymbolAddress((void**)&wdtt,  g_wdtt);

    const size_t SC  = (size_t)Mrows * Cd;
    const size_t SUZ = (size_t)Mrows * TWOD;
    const size_t SDB = (size_t)Mrows * DBLS;
    const size_t SSC = (size_t)Bb * Cd * NCh * NS;

    const float* Xin[2] = { (const float*)d_in[0], (const float*)d_in[1] };
    const float *lng[2], *lnb[2], *Win[2], *Wcv[2], *bcv[2], *Wxp[2],
                *Wdt[2], *bdt[2], *Alog[2], *Dsk[2], *Wout[2];
    for (int s = 0; s < 2; s++) {
        int o = 2 + s * 11;
        lng[s]  = (const float*)d_in[o + 0];
        lnb[s]  = (const float*)d_in[o + 1];
        Win[s]  = (const float*)d_in[o + 2];
        Wcv[s]  = (const float*)d_in[o + 3];
        bcv[s]  = (const float*)d_in[o + 4];
        Wxp[s]  = (const float*)d_in[o + 5];
        Wdt[s]  = (const float*)d_in[o + 6];
        bdt[s]  = (const float*)d_in[o + 7];
        Alog[s] = (const float*)d_in[o + 8];
        Dsk[s]  = (const float*)d_in[o + 9];
        Wout[s] = (const float*)d_in[o + 10];
    }

    // ---- weight prep (transpose + bf16 + zero-pad) ----
    dim3 wtb(32, 8);
    for (int s = 0; s < 2; s++) {
        wt_k<<<dim3(Cd / 32, TWOD / 32), wtb>>>(Win[s],  wint  + s * (size_t)TWOD * Cd, Cd, TWOD, Cd, TWOD);
        wt_k<<<dim3(Cd / 32, Cd / 32),   wtb>>>(Wout[s], woutt + s * (size_t)Cd * Cd,   Cd, Cd,   Cd, Cd);
        wt_k<<<dim3(Cd / 32, 64 / 32),   wtb>>>(Wxp[s],  wxpt  + s * (size_t)64 * Cd,   Cd, 56,   Cd, 64);
        wt_k<<<dim3(64 / 32, Cd / 32),   wtb>>>(Wdt[s],  wdtt  + s * (size_t)Cd * 64,   RK, Cd,   64, Cd);
    }

    // ---- per-stream pre-processing ----
    for (int s = 0; s < 2; s++) {
        ln_stats_k<<<(Mrows + 127) / 128, 128>>>(Xin[s], mean + s * Mrows, rstd + s * Mrows);
        tn_k<<<dim3(Lh / 32, Cd / 32, Bb), dim3(32, 8)>>>(
            Xin[s], mean + s * Mrows, rstd + s * Mrows, lng[s], lnb[s],
            xt + s * SC, xnb + s * SC);

        // in_proj: (8192 x 768) @ (768 x 1536)
        hgemm_k<128, 0><<<dim3(TWOD / 128, Mrows / 128), 256>>>(
            xnb + s * SC, Cd, wint + s * (size_t)TWOD * Cd,
            uz + s * SUZ, TWOD, Cd, nullptr, nullptr);

        conv_silu_k<<<(Mrows * Cd + 255) / 256, 256>>>(
            uz + s * SUZ, Wcv[s], bcv[s], u + s * SC, ub + s * SC);

        // x_proj: (8192 x 768) @ (768 x 64pad) -> dbl fp32 + dtr bf16
        hgemm_k<64, 1><<<dim3(1, Mrows / 128), 256>>>(
            ub + s * SC, Cd, wxpt + s * (size_t)64 * Cd,
            dbl + s * SDB, DBLS, Cd, nullptr, dtrb + s * (size_t)Mrows * 64);

        // dt: softplus((8192 x 64pad) @ (64 x 768) + bdt)
        hgemm_k<128, 2><<<dim3(Cd / 128, Mrows / 128), 256>>>(
            dtrb + s * (size_t)Mrows * 64, 64, wdtt + s * (size_t)Cd * 64,
            dt + s * SC, Cd, 64, bdt[s], nullptr);
    }

    // ---- selective scans (cross-modal C) ----
    for (int s = 0; s < 2; s++) {
        scan1_k<<<dim3(NCh, Bb, Cd / 256), 256>>>(
            dt + s * SC, u + s * SC, dbl + s * SDB, Alog[s],
            P + s * SSC, Hc + s * SSC);
        scan2_k<<<(Bb * Cd + 255) / 256, 256>>>(P + s * SSC, Hc + s * SSC);
        scan3_k<<<dim3(NCh, Bb, Cd / 256), 256>>>(
            dt + s * SC, u + s * SC, dbl + s * SDB, dbl + (1 - s) * SDB,
            Hc + s * SSC, Alog[s], Dsk[s], uz + s * SUZ, yzb + s * SC);
    }

    // ---- out_proj + residual ----
    for (int s = 0; s < 2; s++) {
        float* outp = (float*)d_out + (size_t)s * Mrows * Cd;
        hgemm_k<128, 3><<<dim3(Cd / 128, Mrows / 128), 256>>>(
            yzb + s * SC, Cd, woutt + s * (size_t)Cd * Cd,
            outp, Cd, Cd, xt + s * SC, nullptr);
    }
}